// round 14
// baseline (speedup 1.0000x reference)
#include <cuda_runtime.h>
#include <cuda_fp16.h>
#include <cstdint>

#define TT 2048
#define BB 64
#define HH 128
#define GG 384
#define MTOT (BB * TT)   // 131072
#define NC 32            // pipeline chunks
#define TCH (TT / NC)    // 64 steps per chunk
// fp16 gemm smem: AsH[64][68] + AsL[64][68] + Bs[64][136] (u32)
#define SMEMB ((64 * 68 * 2 + 64 * 136) * 4)

// Scratch (device globals: no runtime allocation allowed)
__device__ float g_gx[(size_t)3 * MTOT * GG];       // per-layer pre-activations
__device__ float g_h[3 * BB * HH];                  // chunk-boundary hidden
__device__ unsigned short g_xhi[(size_t)MTOT * HH]; // X fp16 hi
__device__ unsigned short g_xlo[(size_t)MTOT * HH]; // X fp16 lo (residual)
__device__ unsigned short g_bhi[(size_t)3 * MTOT * HH]; // layer outputs hi
__device__ unsigned short g_blo[(size_t)3 * MTOT * HH]; // layer outputs lo
__device__ uint32_t g_wk16[64 * GG];                // Wk fp16 k-pairs [kp][n]
__device__ uint32_t g_wo16[64 * HH];                // Wo fp16 k-pairs [kp][n]

// ---------- helpers ----------
__device__ __forceinline__ unsigned long long pk2(float x, float y) {
    unsigned long long r;
    asm("mov.b64 %0, {%1, %2};" : "=l"(r) : "f"(x), "f"(y));
    return r;
}
__device__ __forceinline__ void upk2(unsigned long long v, float& x, float& y) {
    asm("mov.b64 {%0, %1}, %2;" : "=f"(x), "=f"(y) : "l"(v));
}
__device__ __forceinline__ unsigned long long ffma2(unsigned long long a,
                                                    unsigned long long b,
                                                    unsigned long long c) {
    unsigned long long d;
    asm("fma.rn.f32x2 %0, %1, %2, %3;" : "=l"(d) : "l"(a), "l"(b), "l"(c));
    return d;
}
__device__ __forceinline__ unsigned long long addf2(unsigned long long a,
                                                    unsigned long long b) {
    unsigned long long d;
    asm("add.rn.f32x2 %0, %1, %2;" : "=l"(d) : "l"(a), "l"(b));
    return d;
}
__device__ __forceinline__ float sigm(float x) {
    return 1.0f / (1.0f + __expf(-x));
}
__device__ __forceinline__ void mma_f16(float* c, uint32_t a0, uint32_t a1,
                                        uint32_t a2, uint32_t a3,
                                        uint32_t b0, uint32_t b1) {
    asm volatile(
        "mma.sync.aligned.m16n8k16.row.col.f32.f16.f16.f32 "
        "{%0,%1,%2,%3}, {%4,%5,%6,%7}, {%8,%9}, {%0,%1,%2,%3};"
        : "+f"(c[0]), "+f"(c[1]), "+f"(c[2]), "+f"(c[3])
        : "r"(a0), "r"(a1), "r"(a2), "r"(a3), "r"(b0), "r"(b1));
}
__device__ __forceinline__ uint32_t packh(float lo, float hi) {
    unsigned short l = __half_as_ushort(__float2half_rn(lo));
    unsigned short h = __half_as_ushort(__float2half_rn(hi));
    return (uint32_t)l | ((uint32_t)h << 16);
}

// ============================================================================
// Weight pack: W[128][N] fp32 -> fp16 k-pairs (lo half = even k).
// ============================================================================
__global__ void __launch_bounds__(256) pack_w(const float* __restrict__ wk,
                                              const float* __restrict__ wo) {
    int i = blockIdx.x * 256 + threadIdx.x;
    if (i < 64 * GG) {
        int kp = i / GG, n = i % GG;
        g_wk16[kp * GG + n] = packh(wk[(2 * kp) * GG + n],
                                    wk[(2 * kp + 1) * GG + n]);
    } else {
        int j = i - 64 * GG;
        if (j < 64 * HH) {
            int kp = j / HH, n = j % HH;
            g_wo16[kp * HH + n] = packh(wo[(2 * kp) * HH + n],
                                        wo[(2 * kp + 1) * HH + n]);
        }
    }
}

// ============================================================================
// X split: fp32 -> fp16 hi + fp16 lo (residual), packed as u32 k-pairs.
// ============================================================================
__global__ void __launch_bounds__(256) split_x(const float* __restrict__ X) {
    size_t i = (size_t)blockIdx.x * 256 + threadIdx.x;
    if (i >= (size_t)MTOT * 64) return;
    float2 v = ((const float2*)X)[i];
    __half hx = __float2half_rn(v.x);
    __half hy = __float2half_rn(v.y);
    float rx = v.x - __half2float(hx);
    float ry = v.y - __half2float(hy);
    ((uint32_t*)g_xhi)[i] = (uint32_t)__half_as_ushort(hx) |
                            ((uint32_t)__half_as_ushort(hy) << 16);
    ((uint32_t*)g_xlo)[i] = packh(rx, ry);
}

// ============================================================================
// K-SPLIT chunked persistent GRU scan: 768 threads, 24 warps.
// Lower 384 threads: gate column c, K in [0,64). Upper 384: same column,
// K in [64,128). Same chip FLOPs, 2x warps per SMSP -> latency hiding.
// Per step: all GEMV-half; upper STS partial; bar; lower combine+sigmoid;
// bar; h-threads (lower c>=256) update h; bar.
// ============================================================================
__global__ void __launch_bounds__(768, 1) gru_scan(
    const float* __restrict__ gx, const float* __restrict__ rec,
    const float* __restrict__ brec, unsigned short* __restrict__ outhi,
    unsigned short* __restrict__ outlo, float* __restrict__ hstate, int t0)
{
    __shared__ __align__(16) float h[HH];
    __shared__ float szr[2 * HH];
    __shared__ float spart[GG];
    __shared__ __align__(16) float sbuf[2][4 * GG];

    const int b = blockIdx.x;
    const int t = threadIdx.x;
    const bool upper = (t >= GG);
    const int c = upper ? (t - GG) : t;
    const bool is_h = (!upper) && (c >= 2 * HH);

    // Weight pairs for this thread's K-half (32 pairs = 64 k-values).
    const int kbase = upper ? 32 : 0;   // pair-index base
    unsigned long long w2[32];
#pragma unroll
    for (int p = 0; p < 32; ++p)
        w2[p] = pk2(rec[(2 * (kbase + p)) * GG + c],
                    rec[(2 * (kbase + p) + 1) * GG + c]);
    const float brc = upper ? 0.0f : brec[c];

    float hreg = 0.0f;
    if (is_h) {
        const int cc = c - 2 * HH;
        hreg = (t0 == 0) ? 0.0f : hstate[b * HH + cc];
        h[cc] = hreg;
    }

    // gx stage: float2 per thread (768 x 8B = 6KB per 4-step group).
    const float2* gx2b = (const float2*)(gx + (size_t)b * TT * GG);
    ((float2*)sbuf[0])[t] = gx2b[(size_t)t0 * 192 + t];
    unsigned short* ohp = outhi + (size_t)b * TT * HH;
    unsigned short* olp = outlo + (size_t)b * TT * HH;
    __syncthreads();

    // h viewed as 32 ulonglong2; this thread's half = 16 of them.
    const ulonglong2* h4base = (const ulonglong2*)h + (upper ? 16 : 0);

    const int tend = t0 + TCH;
    int cur = 0;
    for (int tg = t0; tg < tend; tg += 4) {
        float2 pf;
        const bool havepf = (tg + 4) < tend;
        if (havepf) pf = gx2b[(size_t)(tg + 4) * 192 + t];

#pragma unroll
        for (int k = 0; k < 4; ++k) {
            // GEMV half: 16 LDS.128 + 32 ffma2, 4 independent chains.
            unsigned long long a0 = pk2(brc, 0.0f);
            unsigned long long a1 = 0ull, a2 = 0ull, a3 = 0ull;
#pragma unroll
            for (int j = 0; j < 8; ++j) {
                ulonglong2 p = h4base[2 * j];
                ulonglong2 q = h4base[2 * j + 1];
                a0 = ffma2(p.x, w2[4 * j + 0], a0);
                a1 = ffma2(p.y, w2[4 * j + 1], a1);
                a2 = ffma2(q.x, w2[4 * j + 2], a2);
                a3 = ffma2(q.y, w2[4 * j + 3], a3);
            }
            unsigned long long st = addf2(addf2(a0, a1), addf2(a2, a3));
            float ax, ay;
            upk2(st, ax, ay);
            const float a = ax + ay;

            float gxv = 0.0f;
            if (!upper) gxv = sbuf[cur][k * GG + c];
            else spart[c] = a;
            __syncthreads();                 // bar1: partials visible

            float ah = 0.0f;
            if (!upper) {
                const float atot = a + spart[c];
                if (c < 2 * HH) szr[c] = sigm(atot + gxv);
                else ah = atot;
            }
            __syncthreads();                 // bar2: z/r visible

            float hn = 0.0f;
            if (is_h) {
                const int cc = c - 2 * HH;
                const float z = szr[cc];
                const float r = szr[cc + HH];
                const float pre = gxv + r * ah;
                const float cand = 2.0f * sigm(2.0f * pre) - 1.0f;  // tanh
                hn = fmaf(z, hreg - cand, cand);
                hreg = hn;
                h[cc] = hn;
            }
            if (k == 3 && havepf) ((float2*)sbuf[cur ^ 1])[t] = pf;
            __syncthreads();                 // bar3: h ready for next GEMV

            // Deferred output store: overlaps everyone's next GEMV.
            if (is_h) {
                const int cc = c - 2 * HH;
                __half bh = __float2half_rn(hn);
                float hif = __half2float(bh);
                __half bl = __float2half_rn(hn - hif);
                const size_t o = (size_t)(tg + k) * HH + cc;
                ohp[o] = __half_as_ushort(bh);
                olp[o] = __half_as_ushort(bl);
            }
        }
        cur ^= 1;
    }

    if (is_h) hstate[b * HH + (c - 2 * HH)] = hreg;
}

// ============================================================================
// 2-term fp16 tensor-core GEMM + bias (+ optional sigmoid), BN=128.
// TCH=64: one 64-row tile per batch row per chunk (blockIdx.x = b).
// ============================================================================
__global__ void __launch_bounds__(256, 2) gemm_fp16(
    const uint32_t* __restrict__ Ahi, const uint32_t* __restrict__ Alo,
    const uint32_t* __restrict__ Wpk, const float* __restrict__ bias,
    float* __restrict__ C, int N, int do_sig, int t0)
{
    extern __shared__ uint32_t sm[];
    uint32_t* AsH = sm;                 // [64][68]
    uint32_t* AsL = sm + 64 * 68;       // [64][68]
    uint32_t* Bs  = sm + 2 * 64 * 68;   // [64][136]

    const int tid = threadIdx.x;
    const int m0 = blockIdx.x * TT + t0;
    const int n0 = blockIdx.y * 128;

    const uint4* Ah4 = (const uint4*)(Ahi + (size_t)m0 * 64);
    const uint4* Al4 = (const uint4*)(Alo + (size_t)m0 * 64);
#pragma unroll
    for (int i = 0; i < 4; ++i) {
        int idx = i * 256 + tid;       // 0..1023
        int r = idx >> 4, c4 = idx & 15;
        *(uint4*)(AsH + r * 68 + c4 * 4) = Ah4[idx];
        *(uint4*)(AsL + r * 68 + c4 * 4) = Al4[idx];
    }
    const int N4 = N >> 2;
    const uint4* W4 = (const uint4*)Wpk;
#pragma unroll
    for (int i = 0; i < 8; ++i) {
        int idx = i * 256 + tid;       // 0..2047
        int kp = idx >> 5, c4 = idx & 31;
        *(uint4*)(Bs + kp * 136 + c4 * 4) = W4[(size_t)kp * N4 + (n0 >> 2) + c4];
    }
    __syncthreads();

    const int lane = tid & 31, wid = tid >> 5;
    const int g = lane >> 2, t = lane & 3;
    const int ms = (wid & 3) * 16;
    const int nh = (wid >> 2) * 64;

    float acc[8][4];
#pragma unroll
    for (int s = 0; s < 8; ++s)
#pragma unroll
        for (int q = 0; q < 4; ++q) acc[s][q] = 0.0f;

#pragma unroll
    for (int ks = 0; ks < 8; ++ks) {
        const int kp0 = ks * 8;        // 8 k-pairs = k16 per step
        uint32_t ah0 = AsH[(ms + g) * 68 + kp0 + t];
        uint32_t ah1 = AsH[(ms + g + 8) * 68 + kp0 + t];
        uint32_t ah2 = AsH[(ms + g) * 68 + kp0 + t + 4];
        uint32_t ah3 = AsH[(ms + g + 8) * 68 + kp0 + t + 4];
        uint32_t al0 = AsL[(ms + g) * 68 + kp0 + t];
        uint32_t al1 = AsL[(ms + g + 8) * 68 + kp0 + t];
        uint32_t al2 = AsL[(ms + g) * 68 + kp0 + t + 4];
        uint32_t al3 = AsL[(ms + g + 8) * 68 + kp0 + t + 4];
#pragma unroll
        for (int s = 0; s < 8; ++s) {
            const int bc = nh + s * 8 + g;
            uint32_t b0 = Bs[(kp0 + t) * 136 + bc];
            uint32_t b1 = Bs[(kp0 + t + 4) * 136 + bc];
            mma_f16(acc[s], ah0, ah1, ah2, ah3, b0, b1);
            mma_f16(acc[s], al0, al1, al2, al3, b0, b1);
        }
    }

#pragma unroll
    for (int s = 0; s < 8; ++s) {
        const int col = n0 + nh + s * 8 + 2 * t;
        const float b0v = bias[col], b1v = bias[col + 1];
        float2 v0 = make_float2(acc[s][0] + b0v, acc[s][1] + b1v);
        float2 v1 = make_float2(acc[s][2] + b0v, acc[s][3] + b1v);
        if (do_sig) {
            v0.x = sigm(v0.x); v0.y = sigm(v0.y);
            v1.x = sigm(v1.x); v1.y = sigm(v1.y);
        }
        *(float2*)(C + (size_t)(m0 + ms + g) * N + col) = v0;
        *(float2*)(C + (size_t)(m0 + ms + g + 8) * N + col) = v1;
    }
}

// ============================================================================
// Streams + events (host objects only). Gemm HIGH / scan LOW (R13 layout).
// ============================================================================
struct PipeRes {
    cudaStream_t s[7];   // 0..2 scan (LOW), 3..5 gemm (HIGH), 6 outproj (HIGH)
    cudaEvent_t fork;
    cudaEvent_t eg[3][NC];
    cudaEvent_t es[3][NC];
    cudaEvent_t tail[7];
    PipeRes() {
        int lo, hi;
        cudaDeviceGetStreamPriorityRange(&lo, &hi);
        for (int i = 0; i < 3; ++i)
            cudaStreamCreateWithPriority(&s[i], cudaStreamNonBlocking, lo);
        for (int i = 3; i < 7; ++i)
            cudaStreamCreateWithPriority(&s[i], cudaStreamNonBlocking, hi);
        cudaEventCreateWithFlags(&fork, cudaEventDisableTiming);
        for (int l = 0; l < 3; ++l)
            for (int i = 0; i < NC; ++i) {
                cudaEventCreateWithFlags(&eg[l][i], cudaEventDisableTiming);
                cudaEventCreateWithFlags(&es[l][i], cudaEventDisableTiming);
            }
        for (int i = 0; i < 7; ++i)
            cudaEventCreateWithFlags(&tail[i], cudaEventDisableTiming);
    }
};
static PipeRes P;

extern "C" void kernel_launch(void* const* d_in, const int* in_sizes, int n_in,
                              void* d_out, int out_size)
{
    const float* X    = (const float*)d_in[0];
    const float* Wk   = (const float*)d_in[1];
    const float* Wr   = (const float*)d_in[2];
    const float* bin  = (const float*)d_in[3];
    const float* brec = (const float*)d_in[4];
    const float* Wo   = (const float*)d_in[5];
    const float* bo   = (const float*)d_in[6];
    float* out = (float*)d_out;

    float *gx, *hst;
    unsigned short *xhi, *xlo, *bhi, *blo;
    uint32_t *wk16, *wo16;
    cudaGetSymbolAddress((void**)&gx,   g_gx);
    cudaGetSymbolAddress((void**)&hst,  g_h);
    cudaGetSymbolAddress((void**)&xhi,  g_xhi);
    cudaGetSymbolAddress((void**)&xlo,  g_xlo);
    cudaGetSymbolAddress((void**)&bhi,  g_bhi);
    cudaGetSymbolAddress((void**)&blo,  g_blo);
    cudaGetSymbolAddress((void**)&wk16, g_wk16);
    cudaGetSymbolAddress((void**)&wo16, g_wo16);

    cudaFuncSetAttribute(gemm_fp16, cudaFuncAttributeMaxDynamicSharedMemorySize,
                         SMEMB);

    // Pre-fork: pack W, split X (ordered before all worker streams).
    pack_w<<<(64 * GG + 64 * HH + 255) / 256, 256>>>(Wk, Wo);
    split_x<<<(int)(((size_t)MTOT * 64 + 255) / 256), 256>>>(X);

    cudaEventRecord(P.fork, 0);
    for (int i = 0; i < 7; ++i) cudaStreamWaitEvent(P.s[i], P.fork, 0);

    const dim3 gg(BB, GG / 128);  // 64 x 3
    const dim3 go(BB, HH / 128);  // 64 x 1

    for (int i = 0; i < NC; ++i) {
        for (int l = 0; l < 3; ++l) {
            const uint32_t* Ah = (l == 0) ? (const uint32_t*)xhi
                : (const uint32_t*)(bhi) + (size_t)(l - 1) * MTOT * 64;
            const uint32_t* Al = (l == 0) ? (const uint32_t*)xlo
                : (const uint32_t*)(blo) + (size_t)(l - 1) * MTOT * 64;
            float* gxl = gx + (size_t)l * MTOT * GG;
            unsigned short* ohl = bhi + (size_t)l * MTOT * HH;
            unsigned short* oll = blo + (size_t)l * MTOT * HH;
            float* hl = hst + (size_t)l * BB * HH;
            cudaStream_t sg = P.s[3 + l];
            cudaStream_t sc = P.s[l];

            if (l > 0) cudaStreamWaitEvent(sg, P.es[l - 1][i], 0);
            if (i >= 2) cudaStreamWaitEvent(sg, P.es[l][i - 2], 0);
            gemm_fp16<<<gg, 256, SMEMB, sg>>>(Ah, Al, wk16, bin, gxl,
                                              GG, 0, i * TCH);
            cudaEventRecord(P.eg[l][i], sg);

            cudaStreamWaitEvent(sc, P.eg[l][i], 0);
            gru_scan<<<BB, 768, 0, sc>>>(gxl, Wr, brec, ohl, oll, hl, i * TCH);
            cudaEventRecord(P.es[l][i], sc);
        }
        cudaStreamWaitEvent(P.s[6], P.es[2][i], 0);
        gemm_fp16<<<go, 256, SMEMB, P.s[6]>>>(
            (const uint32_t*)bhi + (size_t)2 * MTOT * 64,
            (const uint32_t*)blo + (size_t)2 * MTOT * 64,
            wo16, bo, out, HH, 1, i * TCH);
    }

    for (int i = 0; i < 7; ++i) {
        cudaEventRecord(P.tail[i], P.s[i]);
        cudaStreamWaitEvent(0, P.tail[i], 0);
    }
}

// round 15
// speedup vs baseline: 1.5963x; 1.5963x over previous
#include <cuda_runtime.h>
#include <cuda_fp16.h>
#include <cstdint>

#define TT 2048
#define BB 64
#define HH 128
#define GG 384
#define MTOT (BB * TT)   // 131072
#define NC 32            // pipeline chunks
#define TCH (TT / NC)    // 64 steps per chunk
// fp16 gemm smem: AsH[64][68] + AsL[64][68] + Bs[64][136] (u32)
#define SMEMB ((64 * 68 * 2 + 64 * 136) * 4)

// Scratch (device globals: no runtime allocation allowed)
__device__ float g_gx[(size_t)3 * MTOT * GG];       // per-layer pre-activations
__device__ float g_h[3 * BB * HH];                  // chunk-boundary hidden
__device__ unsigned short g_xhi[(size_t)MTOT * HH]; // X fp16 hi
__device__ unsigned short g_xlo[(size_t)MTOT * HH]; // X fp16 lo (residual)
__device__ unsigned short g_bhi[(size_t)3 * MTOT * HH]; // layer outputs hi
__device__ unsigned short g_blo[(size_t)3 * MTOT * HH]; // layer outputs lo
__device__ uint32_t g_wk16[64 * GG];                // Wk fp16 k-pairs [kp][n]
__device__ uint32_t g_wo16[64 * HH];                // Wo fp16 k-pairs [kp][n]

// ---------- helpers ----------
__device__ __forceinline__ unsigned long long pk2(float x, float y) {
    unsigned long long r;
    asm("mov.b64 %0, {%1, %2};" : "=l"(r) : "f"(x), "f"(y));
    return r;
}
__device__ __forceinline__ void upk2(unsigned long long v, float& x, float& y) {
    asm("mov.b64 {%0, %1}, %2;" : "=f"(x), "=f"(y) : "l"(v));
}
__device__ __forceinline__ unsigned long long ffma2(unsigned long long a,
                                                    unsigned long long b,
                                                    unsigned long long c) {
    unsigned long long d;
    asm("fma.rn.f32x2 %0, %1, %2, %3;" : "=l"(d) : "l"(a), "l"(b), "l"(c));
    return d;
}
__device__ __forceinline__ unsigned long long addf2(unsigned long long a,
                                                    unsigned long long b) {
    unsigned long long d;
    asm("add.rn.f32x2 %0, %1, %2;" : "=l"(d) : "l"(a), "l"(b));
    return d;
}
// Exact sigmoid (output layer only — error there hits rel_err directly).
__device__ __forceinline__ float sigm(float x) {
    return 1.0f / (1.0f + __expf(-x));
}
// HW tanh (MUFU.TANH, 1 instr, abs err ~2^-11). Scan gates only.
__device__ __forceinline__ float tanh_hw(float x) {
    float y;
    asm("tanh.approx.f32 %0, %1;" : "=f"(y) : "f"(x));
    return y;
}
__device__ __forceinline__ float sigm_hw(float x) {
    return fmaf(tanh_hw(0.5f * x), 0.5f, 0.5f);
}
__device__ __forceinline__ void mma_f16(float* c, uint32_t a0, uint32_t a1,
                                        uint32_t a2, uint32_t a3,
                                        uint32_t b0, uint32_t b1) {
    asm volatile(
        "mma.sync.aligned.m16n8k16.row.col.f32.f16.f16.f32 "
        "{%0,%1,%2,%3}, {%4,%5,%6,%7}, {%8,%9}, {%0,%1,%2,%3};"
        : "+f"(c[0]), "+f"(c[1]), "+f"(c[2]), "+f"(c[3])
        : "r"(a0), "r"(a1), "r"(a2), "r"(a3), "r"(b0), "r"(b1));
}
__device__ __forceinline__ uint32_t packh(float lo, float hi) {
    unsigned short l = __half_as_ushort(__float2half_rn(lo));
    unsigned short h = __half_as_ushort(__float2half_rn(hi));
    return (uint32_t)l | ((uint32_t)h << 16);
}

// ============================================================================
// Weight pack: W[128][N] fp32 -> fp16 k-pairs (lo half = even k).
// ============================================================================
__global__ void __launch_bounds__(256) pack_w(const float* __restrict__ wk,
                                              const float* __restrict__ wo) {
    int i = blockIdx.x * 256 + threadIdx.x;
    if (i < 64 * GG) {
        int kp = i / GG, n = i % GG;
        g_wk16[kp * GG + n] = packh(wk[(2 * kp) * GG + n],
                                    wk[(2 * kp + 1) * GG + n]);
    } else {
        int j = i - 64 * GG;
        if (j < 64 * HH) {
            int kp = j / HH, n = j % HH;
            g_wo16[kp * HH + n] = packh(wo[(2 * kp) * HH + n],
                                        wo[(2 * kp + 1) * HH + n]);
        }
    }
}

// ============================================================================
// X split: fp32 -> fp16 hi + fp16 lo (residual), packed as u32 k-pairs.
// ============================================================================
__global__ void __launch_bounds__(256) split_x(const float* __restrict__ X) {
    size_t i = (size_t)blockIdx.x * 256 + threadIdx.x;
    if (i >= (size_t)MTOT * 64) return;
    float2 v = ((const float2*)X)[i];
    __half hx = __float2half_rn(v.x);
    __half hy = __float2half_rn(v.y);
    float rx = v.x - __half2float(hx);
    float ry = v.y - __half2float(hy);
    ((uint32_t*)g_xhi)[i] = (uint32_t)__half_as_ushort(hx) |
                            ((uint32_t)__half_as_ushort(hy) << 16);
    ((uint32_t*)g_xlo)[i] = packh(rx, ry);
}

// ============================================================================
// Chunked persistent GRU scan (R13-proven structure) with HW-tanh gates.
// One CTA per batch row, 384 threads, steps [t0, t0+TCH).
// ============================================================================
__global__ void __launch_bounds__(GG, 1) gru_scan(
    const float* __restrict__ gx, const float* __restrict__ rec,
    const float* __restrict__ brec, unsigned short* __restrict__ outhi,
    unsigned short* __restrict__ outlo, float* __restrict__ hstate, int t0)
{
    __shared__ __align__(16) float h[HH];
    __shared__ float szr[2 * HH];
    __shared__ __align__(16) float sbuf[2][4 * GG];

    const int b = blockIdx.x;
    const int c = threadIdx.x;
    const bool is_h = (c >= 2 * HH);

    unsigned long long w2[64];
#pragma unroll
    for (int p = 0; p < 64; ++p)
        w2[p] = pk2(rec[(2 * p) * GG + c], rec[(2 * p + 1) * GG + c]);
    const float brc = brec[c];

    float hreg = 0.0f;
    if (is_h) {
        const int cc = c - 2 * HH;
        hreg = (t0 == 0) ? 0.0f : hstate[b * HH + cc];
        h[cc] = hreg;
    }

    const float4* gx4b = (const float4*)(gx + (size_t)b * TT * GG);
    ((float4*)sbuf[0])[c] = gx4b[(size_t)t0 * 96 + c];
    unsigned short* ohp = outhi + (size_t)b * TT * HH;
    unsigned short* olp = outlo + (size_t)b * TT * HH;
    __syncthreads();

    const int tend = t0 + TCH;
    int cur = 0;
    for (int tg = t0; tg < tend; tg += 4) {
        float4 pf;
        const bool havepf = (tg + 4) < tend;
        if (havepf) pf = gx4b[(size_t)(tg + 4) * 96 + c];

#pragma unroll
        for (int k = 0; k < 4; ++k) {
            unsigned long long a0 = pk2(brc, 0.0f);
            unsigned long long a1 = 0ull, a2 = 0ull, a3 = 0ull;
            const ulonglong2* h4 = (const ulonglong2*)h;
#pragma unroll
            for (int j = 0; j < 16; ++j) {
                ulonglong2 p = h4[2 * j];
                ulonglong2 q = h4[2 * j + 1];
                a0 = ffma2(p.x, w2[4 * j + 0], a0);
                a1 = ffma2(p.y, w2[4 * j + 1], a1);
                a2 = ffma2(q.x, w2[4 * j + 2], a2);
                a3 = ffma2(q.y, w2[4 * j + 3], a3);
            }
            unsigned long long st = addf2(addf2(a0, a1), addf2(a2, a3));
            float ax, ay;
            upk2(st, ax, ay);
            float a = ax + ay;

            const float gxv = sbuf[cur][k * GG + c];
            if (!is_h) szr[c] = sigm_hw(a + gxv);   // z, r via HW tanh
            __syncthreads();

            float hn = 0.0f;
            if (is_h) {
                const int cc = c - 2 * HH;
                float z = szr[cc];
                float r = szr[cc + HH];
                float pre = gxv + r * a;
                float cand = tanh_hw(pre);          // 1 MUFU on the CP
                hn = fmaf(z, hreg - cand, cand);
                hreg = hn;
                h[cc] = hn;
            }
            if (k == 3 && havepf) ((float4*)sbuf[cur ^ 1])[c] = pf;
            __syncthreads();

            // Deferred output store: overlaps the z/r warps' next GEMV.
            if (is_h) {
                const int cc = c - 2 * HH;
                __half bh = __float2half_rn(hn);
                float hif = __half2float(bh);
                __half bl = __float2half_rn(hn - hif);
                const size_t o = (size_t)(tg + k) * HH + cc;
                ohp[o] = __half_as_ushort(bh);
                olp[o] = __half_as_ushort(bl);
            }
        }
        cur ^= 1;
    }

    if (is_h) hstate[b * HH + (c - 2 * HH)] = hreg;
}

// ============================================================================
// 2-term fp16 tensor-core GEMM + bias (+ optional EXACT sigmoid), BN=128.
// TCH=64: one 64-row tile per batch row per chunk (blockIdx.x = b).
// ============================================================================
__global__ void __launch_bounds__(256, 2) gemm_fp16(
    const uint32_t* __restrict__ Ahi, const uint32_t* __restrict__ Alo,
    const uint32_t* __restrict__ Wpk, const float* __restrict__ bias,
    float* __restrict__ C, int N, int do_sig, int t0)
{
    extern __shared__ uint32_t sm[];
    uint32_t* AsH = sm;                 // [64][68]
    uint32_t* AsL = sm + 64 * 68;       // [64][68]
    uint32_t* Bs  = sm + 2 * 64 * 68;   // [64][136]

    const int tid = threadIdx.x;
    const int m0 = blockIdx.x * TT + t0;
    const int n0 = blockIdx.y * 128;

    const uint4* Ah4 = (const uint4*)(Ahi + (size_t)m0 * 64);
    const uint4* Al4 = (const uint4*)(Alo + (size_t)m0 * 64);
#pragma unroll
    for (int i = 0; i < 4; ++i) {
        int idx = i * 256 + tid;       // 0..1023
        int r = idx >> 4, c4 = idx & 15;
        *(uint4*)(AsH + r * 68 + c4 * 4) = Ah4[idx];
        *(uint4*)(AsL + r * 68 + c4 * 4) = Al4[idx];
    }
    const int N4 = N >> 2;
    const uint4* W4 = (const uint4*)Wpk;
#pragma unroll
    for (int i = 0; i < 8; ++i) {
        int idx = i * 256 + tid;       // 0..2047
        int kp = idx >> 5, c4 = idx & 31;
        *(uint4*)(Bs + kp * 136 + c4 * 4) = W4[(size_t)kp * N4 + (n0 >> 2) + c4];
    }
    __syncthreads();

    const int lane = tid & 31, wid = tid >> 5;
    const int g = lane >> 2, t = lane & 3;
    const int ms = (wid & 3) * 16;
    const int nh = (wid >> 2) * 64;

    float acc[8][4];
#pragma unroll
    for (int s = 0; s < 8; ++s)
#pragma unroll
        for (int q = 0; q < 4; ++q) acc[s][q] = 0.0f;

#pragma unroll
    for (int ks = 0; ks < 8; ++ks) {
        const int kp0 = ks * 8;        // 8 k-pairs = k16 per step
        uint32_t ah0 = AsH[(ms + g) * 68 + kp0 + t];
        uint32_t ah1 = AsH[(ms + g + 8) * 68 + kp0 + t];
        uint32_t ah2 = AsH[(ms + g) * 68 + kp0 + t + 4];
        uint32_t ah3 = AsH[(ms + g + 8) * 68 + kp0 + t + 4];
        uint32_t al0 = AsL[(ms + g) * 68 + kp0 + t];
        uint32_t al1 = AsL[(ms + g + 8) * 68 + kp0 + t];
        uint32_t al2 = AsL[(ms + g) * 68 + kp0 + t + 4];
        uint32_t al3 = AsL[(ms + g + 8) * 68 + kp0 + t + 4];
#pragma unroll
        for (int s = 0; s < 8; ++s) {
            const int bc = nh + s * 8 + g;
            uint32_t b0 = Bs[(kp0 + t) * 136 + bc];
            uint32_t b1 = Bs[(kp0 + t + 4) * 136 + bc];
            mma_f16(acc[s], ah0, ah1, ah2, ah3, b0, b1);
            mma_f16(acc[s], al0, al1, al2, al3, b0, b1);
        }
    }

#pragma unroll
    for (int s = 0; s < 8; ++s) {
        const int col = n0 + nh + s * 8 + 2 * t;
        const float b0v = bias[col], b1v = bias[col + 1];
        float2 v0 = make_float2(acc[s][0] + b0v, acc[s][1] + b1v);
        float2 v1 = make_float2(acc[s][2] + b0v, acc[s][3] + b1v);
        if (do_sig) {
            v0.x = sigm(v0.x); v0.y = sigm(v0.y);
            v1.x = sigm(v1.x); v1.y = sigm(v1.y);
        }
        *(float2*)(C + (size_t)(m0 + ms + g) * N + col) = v0;
        *(float2*)(C + (size_t)(m0 + ms + g + 8) * N + col) = v1;
    }
}

// ============================================================================
// Streams + events (host objects only). Gemm HIGH / scan LOW (R13 layout).
// ============================================================================
struct PipeRes {
    cudaStream_t s[7];   // 0..2 scan (LOW), 3..5 gemm (HIGH), 6 outproj (HIGH)
    cudaEvent_t fork;
    cudaEvent_t eg[3][NC];
    cudaEvent_t es[3][NC];
    cudaEvent_t tail[7];
    PipeRes() {
        int lo, hi;
        cudaDeviceGetStreamPriorityRange(&lo, &hi);
        for (int i = 0; i < 3; ++i)
            cudaStreamCreateWithPriority(&s[i], cudaStreamNonBlocking, lo);
        for (int i = 3; i < 7; ++i)
            cudaStreamCreateWithPriority(&s[i], cudaStreamNonBlocking, hi);
        cudaEventCreateWithFlags(&fork, cudaEventDisableTiming);
        for (int l = 0; l < 3; ++l)
            for (int i = 0; i < NC; ++i) {
                cudaEventCreateWithFlags(&eg[l][i], cudaEventDisableTiming);
                cudaEventCreateWithFlags(&es[l][i], cudaEventDisableTiming);
            }
        for (int i = 0; i < 7; ++i)
            cudaEventCreateWithFlags(&tail[i], cudaEventDisableTiming);
    }
};
static PipeRes P;

extern "C" void kernel_launch(void* const* d_in, const int* in_sizes, int n_in,
                              void* d_out, int out_size)
{
    const float* X    = (const float*)d_in[0];
    const float* Wk   = (const float*)d_in[1];
    const float* Wr   = (const float*)d_in[2];
    const float* bin  = (const float*)d_in[3];
    const float* brec = (const float*)d_in[4];
    const float* Wo   = (const float*)d_in[5];
    const float* bo   = (const float*)d_in[6];
    float* out = (float*)d_out;

    float *gx, *hst;
    unsigned short *xhi, *xlo, *bhi, *blo;
    uint32_t *wk16, *wo16;
    cudaGetSymbolAddress((void**)&gx,   g_gx);
    cudaGetSymbolAddress((void**)&hst,  g_h);
    cudaGetSymbolAddress((void**)&xhi,  g_xhi);
    cudaGetSymbolAddress((void**)&xlo,  g_xlo);
    cudaGetSymbolAddress((void**)&bhi,  g_bhi);
    cudaGetSymbolAddress((void**)&blo,  g_blo);
    cudaGetSymbolAddress((void**)&wk16, g_wk16);
    cudaGetSymbolAddress((void**)&wo16, g_wo16);

    cudaFuncSetAttribute(gemm_fp16, cudaFuncAttributeMaxDynamicSharedMemorySize,
                         SMEMB);

    // Pre-fork: pack W, split X (ordered before all worker streams).
    pack_w<<<(64 * GG + 64 * HH + 255) / 256, 256>>>(Wk, Wo);
    split_x<<<(int)(((size_t)MTOT * 64 + 255) / 256), 256>>>(X);

    cudaEventRecord(P.fork, 0);
    for (int i = 0; i < 7; ++i) cudaStreamWaitEvent(P.s[i], P.fork, 0);

    const dim3 gg(BB, GG / 128);  // 64 x 3
    const dim3 go(BB, HH / 128);  // 64 x 1

    for (int i = 0; i < NC; ++i) {
        for (int l = 0; l < 3; ++l) {
            const uint32_t* Ah = (l == 0) ? (const uint32_t*)xhi
                : (const uint32_t*)(bhi) + (size_t)(l - 1) * MTOT * 64;
            const uint32_t* Al = (l == 0) ? (const uint32_t*)xlo
                : (const uint32_t*)(blo) + (size_t)(l - 1) * MTOT * 64;
            float* gxl = gx + (size_t)l * MTOT * GG;
            unsigned short* ohl = bhi + (size_t)l * MTOT * HH;
            unsigned short* oll = blo + (size_t)l * MTOT * HH;
            float* hl = hst + (size_t)l * BB * HH;
            cudaStream_t sg = P.s[3 + l];
            cudaStream_t sc = P.s[l];

            if (l > 0) cudaStreamWaitEvent(sg, P.es[l - 1][i], 0);
            if (i >= 2) cudaStreamWaitEvent(sg, P.es[l][i - 2], 0);
            gemm_fp16<<<gg, 256, SMEMB, sg>>>(Ah, Al, wk16, bin, gxl,
                                              GG, 0, i * TCH);
            cudaEventRecord(P.eg[l][i], sg);

            cudaStreamWaitEvent(sc, P.eg[l][i], 0);
            gru_scan<<<BB, GG, 0, sc>>>(gxl, Wr, brec, ohl, oll, hl, i * TCH);
            cudaEventRecord(P.es[l][i], sc);
        }
        cudaStreamWaitEvent(P.s[6], P.es[2][i], 0);
        gemm_fp16<<<go, 256, SMEMB, P.s[6]>>>(
            (const uint32_t*)bhi + (size_t)2 * MTOT * 64,
            (const uint32_t*)blo + (size_t)2 * MTOT * 64,
            wo16, bo, out, HH, 1, i * TCH);
    }

    for (int i = 0; i < 7; ++i) {
        cudaEventRecord(P.tail[i], P.s[i]);
        cudaStreamWaitEvent(0, P.tail[i], 0);
    }
}